// round 9
// baseline (speedup 1.0000x reference)
#include <cuda_runtime.h>
#include <cuda_fp16.h>

#define N_  4
#define C_  128
#define HW_ 4096
#define W_  64

union Half4 {
    uint2   u;
    __half2 h[2];
};

// ---------------------------------------------------------------------------
// Fused kernel, 2-way position split for phase overlap.
// Block b: n = b>>6, channel-quad cq = (b>>1)&31, half = b&1.
// 512 threads. Each block stages the FULL half4 tile s[j] = half4(x[ch0..3][j])
// (duplicated between the two half-blocks; +8MB L2, enables 2 blocks/SM with
// independent barriers so staging of one overlaps gather of the other).
// Each block computes output positions [half*2048, half*2048+2048).
// Thread t: 4 consecutive positions k = half*2048 + 4t .. +3.
// out = w0*x[c] + w1*x[c+1] + w2*x[c+64] + w3*x[c+65],
// w = outer([1-fx, fx], [fx, fy]) * valid  (valid over ALL 4 grids)
// ---------------------------------------------------------------------------
__global__ __launch_bounds__(512, 2)
void fused_kernel(const float* __restrict__ x,
                  const float* __restrict__ grid,
                  float* __restrict__ out) {
    __shared__ uint2 s[HW_];   // 32 KB: half4 per position

    const int tid  = threadIdx.x;            // 0..511
    const int b    = blockIdx.x;             // 0..255
    const int n    = b >> 6;                 // 0..3
    const int cq   = (b >> 1) & 31;          // 0..31
    const int half = b & 1;                  // 0..1
    const int ch0  = cq * 4;
    const int kb   = half * (HW_ / 2);       // first output position

    const float4* r0 = (const float4*)(x + (size_t)(n * C_ + ch0 + 0) * HW_);
    const float4* r1 = (const float4*)(x + (size_t)(n * C_ + ch0 + 1) * HW_);
    const float4* r2 = (const float4*)(x + (size_t)(n * C_ + ch0 + 2) * HW_);
    const float4* r3 = (const float4*)(x + (size_t)(n * C_ + ch0 + 3) * HW_);

    // ---- staging loads: chunks i = tid, tid+512 (full tile; all LDG.128)
    float4 v0[2], v1[2], v2[2], v3[2];
#pragma unroll
    for (int m = 0; m < 2; ++m) {
        int i = tid + 512 * m;
        v0[m] = __ldg(r0 + i);
        v1[m] = __ldg(r1 + i);
        v2[m] = __ldg(r2 + i);
        v3[m] = __ldg(r3 + i);
    }

    // ---- tap loads: positions kb+4t..kb+4t+3, all 4 grids (validity .all(0))
    const float4* g4 = (const float4*)grid;   // row r at offset r*HW_/2 float4s
    float4 G[4][2];
#pragma unroll
    for (int r = 0; r < 4; ++r) {
        const float4* gr = g4 + r * (HW_ / 2) + kb / 2;
        G[r][0] = __ldg(gr + 2 * tid);
        G[r][1] = __ldg(gr + 2 * tid + 1);
    }

    // ---- stage as half4 quads (2x uint4 STS.128 per chunk)
#pragma unroll
    for (int m = 0; m < 2; ++m) {
        int i = tid + 512 * m;
        Half4 q0, q1, q2, q3;
        q0.h[0] = __floats2half2_rn(v0[m].x, v1[m].x);  q0.h[1] = __floats2half2_rn(v2[m].x, v3[m].x);
        q1.h[0] = __floats2half2_rn(v0[m].y, v1[m].y);  q1.h[1] = __floats2half2_rn(v2[m].y, v3[m].y);
        q2.h[0] = __floats2half2_rn(v0[m].z, v1[m].z);  q2.h[1] = __floats2half2_rn(v2[m].z, v3[m].z);
        q3.h[0] = __floats2half2_rn(v0[m].w, v1[m].w);  q3.h[1] = __floats2half2_rn(v2[m].w, v3[m].w);
        uint4* sd = (uint4*)&s[4 * i];
        sd[0] = make_uint4(q0.u.x, q0.u.y, q1.u.x, q1.u.y);
        sd[1] = make_uint4(q2.u.x, q2.u.y, q3.u.x, q3.u.y);
    }

    // ---- tap math (register-only; overlaps barrier wait)
    int   c0[4];
    float fx[4], fy[4];
#pragma unroll
    for (int p = 0; p < 4; ++p) {
        float2 gg[4];
#pragma unroll
        for (int r = 0; r < 4; ++r) {
            float4 h = G[r][p >> 1];
            gg[r] = (p & 1) ? make_float2(h.z, h.w) : make_float2(h.x, h.y);
        }
        bool valid = true;
#pragma unroll
        for (int r = 0; r < 4; ++r)
            valid = valid && (gg[r].x >= -0.001f) && (gg[r].x <= 63.001f)
                          && (gg[r].y >= -0.001f) && (gg[r].y <= 63.001f);
        float2 go = gg[n];
        float xx = fminf(fmaxf(go.x, 0.001f), 62.999f);
        float yy = fminf(fmaxf(go.y, 0.001f), 62.999f);
        float flx = floorf(xx);
        float fly = floorf(yy);
        c0[p] = (int)flx * W_ + (int)fly;
        fx[p] = valid ? (xx - flx) : 0.f;
        fy[p] = valid ? (yy - fly) : 0.f;
    }
    __syncthreads();

    // ---- gather + math: 4 positions x 4 corners (LDS.64), fp32 accumulate
    float4 oc0, oc1, oc2, oc3;
    float* po0 = (float*)&oc0;
    float* po1 = (float*)&oc1;
    float* po2 = (float*)&oc2;
    float* po3 = (float*)&oc3;
#pragma unroll
    for (int p = 0; p < 4; ++p) {
        int c = c0[p];
        Half4 t0, t1, t2, t3;
        t0.u = s[c];
        t1.u = s[c + 1];
        t2.u = s[c + 64];
        t3.u = s[c + 65];

        float w0 = (1.f - fx[p]) * fx[p];
        float w1 = (1.f - fx[p]) * fy[p];
        float w2 = fx[p] * fx[p];
        float w3 = fx[p] * fy[p];

        float2 a01 = __half22float2(t0.h[0]), a23 = __half22float2(t0.h[1]);
        float2 b01 = __half22float2(t1.h[0]), b23 = __half22float2(t1.h[1]);
        float2 c01 = __half22float2(t2.h[0]), c23 = __half22float2(t2.h[1]);
        float2 d01 = __half22float2(t3.h[0]), d23 = __half22float2(t3.h[1]);

        po0[p] = w0 * a01.x + w1 * b01.x + w2 * c01.x + w3 * d01.x;
        po1[p] = w0 * a01.y + w1 * b01.y + w2 * c01.y + w3 * d01.y;
        po2[p] = w0 * a23.x + w1 * b23.x + w2 * c23.x + w3 * d23.x;
        po3[p] = w0 * a23.y + w1 * b23.y + w2 * c23.y + w3 * d23.y;
    }

    float4* ob = (float4*)(out + (size_t)(n * C_ + ch0) * HW_);
    const int q  = HW_ / 4;          // float4 per channel row
    const int ko = kb / 4 + tid;     // float4 index within row
    ob[0 * q + ko] = oc0;
    ob[1 * q + ko] = oc1;
    ob[2 * q + ko] = oc2;
    ob[3 * q + ko] = oc3;
}

extern "C" void kernel_launch(void* const* d_in, const int* in_sizes, int n_in,
                              void* d_out, int out_size) {
    const float* x    = (const float*)d_in[0];   // (4, 128, 4096) f32
    const float* grid = (const float*)d_in[1];   // (4, 64, 64, 2) f32
    float* out = (float*)d_out;                  // (4, 128, 4096) f32

    fused_kernel<<<N_ * (C_ / 4) * 2, 512>>>(x, grid, out);
}

// round 10
// speedup vs baseline: 1.0087x; 1.0087x over previous
#include <cuda_runtime.h>
#include <cuda_fp16.h>

#define N_  4
#define C_  128
#define HW_ 4096
#define W_  64

union Half4 {
    uint2   u;
    __half2 h[2];
};

// ---------------------------------------------------------------------------
// Fused kernel: 128 blocks x 512 threads, 2 blocks/SM (independent barriers
// -> staging phase of one block overlaps gather phase of the other).
// Block owns one (n, channel-quad) tile:
//   stage s[j] = half4(x[ch0..ch0+3][j]) once (32 KB),
//   compute all 4096 positions, 8 per thread in 2 groups of 4 consecutive.
// All gmem traffic 128-bit. Gather: one LDS.64 per corner serves 4 channels.
// out = w0*x[c] + w1*x[c+1] + w2*x[c+64] + w3*x[c+65],
// w = outer([1-fx, fx], [fx, fy]) * valid  (valid over ALL 4 grids)
// ---------------------------------------------------------------------------
__global__ __launch_bounds__(512, 2)
void fused_kernel(const float* __restrict__ x,
                  const float* __restrict__ grid,
                  float* __restrict__ out) {
    __shared__ uint2 s[HW_];   // 32 KB

    const int tid = threadIdx.x;          // 0..511
    const int n   = blockIdx.x >> 5;      // 0..3
    const int ch0 = (blockIdx.x & 31) * 4;

    const float4* r0 = (const float4*)(x + (size_t)(n * C_ + ch0 + 0) * HW_);
    const float4* r1 = (const float4*)(x + (size_t)(n * C_ + ch0 + 1) * HW_);
    const float4* r2 = (const float4*)(x + (size_t)(n * C_ + ch0 + 2) * HW_);
    const float4* r3 = (const float4*)(x + (size_t)(n * C_ + ch0 + 3) * HW_);

    // ---- staging: thread loads float4 chunks i = tid, tid+512 of each row
    float4 v0[2], v1[2], v2[2], v3[2];
#pragma unroll
    for (int m = 0; m < 2; ++m) {
        int i = tid + 512 * m;
        v0[m] = __ldg(r0 + i);
        v1[m] = __ldg(r1 + i);
        v2[m] = __ldg(r2 + i);
        v3[m] = __ldg(r3 + i);
    }
#pragma unroll
    for (int m = 0; m < 2; ++m) {
        int i = tid + 512 * m;
        Half4 q0, q1, q2, q3;
        q0.h[0] = __floats2half2_rn(v0[m].x, v1[m].x);  q0.h[1] = __floats2half2_rn(v2[m].x, v3[m].x);
        q1.h[0] = __floats2half2_rn(v0[m].y, v1[m].y);  q1.h[1] = __floats2half2_rn(v2[m].y, v3[m].y);
        q2.h[0] = __floats2half2_rn(v0[m].z, v1[m].z);  q2.h[1] = __floats2half2_rn(v2[m].z, v3[m].z);
        q3.h[0] = __floats2half2_rn(v0[m].w, v1[m].w);  q3.h[1] = __floats2half2_rn(v2[m].w, v3[m].w);
        uint4* sd = (uint4*)&s[4 * i];
        sd[0] = make_uint4(q0.u.x, q0.u.y, q1.u.x, q1.u.y);
        sd[1] = make_uint4(q2.u.x, q2.u.y, q3.u.x, q3.u.y);
    }
    __syncthreads();

    const float4* g4 = (const float4*)grid;   // grid row r starts at r*HW_/2
    float4* ob = (float4*)(out + (size_t)(n * C_ + ch0) * HW_);
    const int q = HW_ / 4;   // float4 per channel row

    // ---- two groups of 4 consecutive positions each
#pragma unroll
    for (int g = 0; g < 2; ++g) {
        const int t4 = tid + 512 * g;    // float4-group index: positions 4*t4..4*t4+3

        // tap loads (group 1's loads issue after barrier, overlapping group 0's LDS)
        float4 G[4][2];
#pragma unroll
        for (int r = 0; r < 4; ++r) {
            G[r][0] = __ldg(g4 + r * (HW_ / 2) + 2 * t4);
            G[r][1] = __ldg(g4 + r * (HW_ / 2) + 2 * t4 + 1);
        }

        int   c0[4];
        float fx[4], fy[4];
#pragma unroll
        for (int p = 0; p < 4; ++p) {
            float2 gg[4];
#pragma unroll
            for (int r = 0; r < 4; ++r) {
                float4 h = G[r][p >> 1];
                gg[r] = (p & 1) ? make_float2(h.z, h.w) : make_float2(h.x, h.y);
            }
            bool valid = true;
#pragma unroll
            for (int r = 0; r < 4; ++r)
                valid = valid && (gg[r].x >= -0.001f) && (gg[r].x <= 63.001f)
                              && (gg[r].y >= -0.001f) && (gg[r].y <= 63.001f);
            float2 go = gg[n];
            float xx = fminf(fmaxf(go.x, 0.001f), 62.999f);
            float yy = fminf(fmaxf(go.y, 0.001f), 62.999f);
            float flx = floorf(xx);
            float fly = floorf(yy);
            c0[p] = (int)flx * W_ + (int)fly;
            fx[p] = valid ? (xx - flx) : 0.f;
            fy[p] = valid ? (yy - fly) : 0.f;
        }

        float4 oc0, oc1, oc2, oc3;
        float* po0 = (float*)&oc0;
        float* po1 = (float*)&oc1;
        float* po2 = (float*)&oc2;
        float* po3 = (float*)&oc3;
#pragma unroll
        for (int p = 0; p < 4; ++p) {
            int c = c0[p];
            Half4 t0, t1, t2, t3;
            t0.u = s[c];
            t1.u = s[c + 1];
            t2.u = s[c + 64];
            t3.u = s[c + 65];

            float w0 = (1.f - fx[p]) * fx[p];
            float w1 = (1.f - fx[p]) * fy[p];
            float w2 = fx[p] * fx[p];
            float w3 = fx[p] * fy[p];

            float2 a01 = __half22float2(t0.h[0]), a23 = __half22float2(t0.h[1]);
            float2 b01 = __half22float2(t1.h[0]), b23 = __half22float2(t1.h[1]);
            float2 c01 = __half22float2(t2.h[0]), c23 = __half22float2(t2.h[1]);
            float2 d01 = __half22float2(t3.h[0]), d23 = __half22float2(t3.h[1]);

            po0[p] = w0 * a01.x + w1 * b01.x + w2 * c01.x + w3 * d01.x;
            po1[p] = w0 * a01.y + w1 * b01.y + w2 * c01.y + w3 * d01.y;
            po2[p] = w0 * a23.x + w1 * b23.x + w2 * c23.x + w3 * d23.x;
            po3[p] = w0 * a23.y + w1 * b23.y + w2 * c23.y + w3 * d23.y;
        }

        ob[0 * q + t4] = oc0;
        ob[1 * q + t4] = oc1;
        ob[2 * q + t4] = oc2;
        ob[3 * q + t4] = oc3;
    }
}

extern "C" void kernel_launch(void* const* d_in, const int* in_sizes, int n_in,
                              void* d_out, int out_size) {
    const float* x    = (const float*)d_in[0];   // (4, 128, 4096) f32
    const float* grid = (const float*)d_in[1];   // (4, 64, 64, 2) f32
    float* out = (float*)d_out;                  // (4, 128, 4096) f32

    fused_kernel<<<N_ * (C_ / 4), 512>>>(x, grid, out);
}

// round 11
// speedup vs baseline: 1.0328x; 1.0239x over previous
#include <cuda_runtime.h>
#include <cuda_fp16.h>

#define N_  4
#define C_  128
#define HW_ 4096
#define W_  64

union Half4 {
    uint2   u;
    __half2 h[2];
};

// Packed tap per (n,k): .x = c0 (low 16) | fx_unorm16 (high 16), .y = fy_unorm16.
// Invalid positions: fx = fy = 0 -> all four coeffs exactly 0.
__device__ uint2 g_tap[N_ * HW_];

// ---------------------------------------------------------------------------
// Kernel 1: pack taps. 2048 threads, thread handles positions 2t, 2t+1.
// valid requires in-range in ALL 4 grids (.all(0) in reference).
// ---------------------------------------------------------------------------
__global__ void prep_kernel(const float* __restrict__ grid) {
    int t = blockIdx.x * blockDim.x + threadIdx.x;   // 0..2047
    if (t >= HW_ / 2) return;

    const float4* g4 = (const float4*)grid;          // grid row r: r*HW_/2 float4s
    float4 G[4];
#pragma unroll
    for (int r = 0; r < 4; ++r) G[r] = __ldg(g4 + r * (HW_ / 2) + t);

    uint4 outv[N_];
#pragma unroll
    for (int p = 0; p < 2; ++p) {
        float2 gg[4];
#pragma unroll
        for (int r = 0; r < 4; ++r)
            gg[r] = p ? make_float2(G[r].z, G[r].w) : make_float2(G[r].x, G[r].y);
        bool valid = true;
#pragma unroll
        for (int r = 0; r < 4; ++r)
            valid = valid && (gg[r].x >= -0.001f) && (gg[r].x <= 63.001f)
                          && (gg[r].y >= -0.001f) && (gg[r].y <= 63.001f);
#pragma unroll
        for (int n = 0; n < N_; ++n) {
            float xx = fminf(fmaxf(gg[n].x, 0.001f), 62.999f);
            float yy = fminf(fmaxf(gg[n].y, 0.001f), 62.999f);
            float flx = floorf(xx);
            float fly = floorf(yy);
            unsigned c0  = (unsigned)((int)flx * W_ + (int)fly);
            unsigned fxu = valid ? (unsigned)__float2int_rn((xx - flx) * 65535.f) : 0u;
            unsigned fyu = valid ? (unsigned)__float2int_rn((yy - fly) * 65535.f) : 0u;
            if (p == 0) { outv[n].x = c0 | (fxu << 16); outv[n].y = fyu; }
            else        { outv[n].z = c0 | (fxu << 16); outv[n].w = fyu; }
        }
    }
#pragma unroll
    for (int n = 0; n < N_; ++n)
        *(uint4*)&g_tap[n * HW_ + 2 * t] = outv[n];
}

// ---------------------------------------------------------------------------
// Kernel 2: 128 blocks x 1024 threads, one block per (n, channel-quad).
// Smem: s[j] = half4(x[ch0..ch0+3][j])  -> one LDS.64 per corner serves 4 ch.
// Thread t: 4 consecutive positions 4t..4t+3; all gmem ops 128-bit:
//   stage 4x LDG.128 + 2x STS.128, taps 2x LDG.128, out 4x STG.128.
// out = w0*x[c] + w1*x[c+1] + w2*x[c+64] + w3*x[c+65],
// w = outer([1-fx, fx], [fx, fy])  (validity pre-folded into fx,fy)
// ---------------------------------------------------------------------------
__global__ __launch_bounds__(1024, 1)
void gather_kernel(const float* __restrict__ x, float* __restrict__ out) {
    __shared__ uint2 s[HW_];   // 32 KB

    const int tid = threadIdx.x;          // 0..1023
    const int n   = blockIdx.x >> 5;      // 0..3
    const int ch0 = (blockIdx.x & 31) * 4;

    const float4* r0 = (const float4*)(x + (size_t)(n * C_ + ch0 + 0) * HW_);
    const float4* r1 = (const float4*)(x + (size_t)(n * C_ + ch0 + 1) * HW_);
    const float4* r2 = (const float4*)(x + (size_t)(n * C_ + ch0 + 2) * HW_);
    const float4* r3 = (const float4*)(x + (size_t)(n * C_ + ch0 + 3) * HW_);

    // ---- staging + tap loads (all independent; max MLP)
    float4 v0 = __ldg(r0 + tid);
    float4 v1 = __ldg(r1 + tid);
    float4 v2 = __ldg(r2 + tid);
    float4 v3 = __ldg(r3 + tid);

    const uint4* tp = (const uint4*)(g_tap + n * HW_);
    uint4 T01 = __ldg(tp + 2 * tid);       // taps for positions 4t, 4t+1
    uint4 T23 = __ldg(tp + 2 * tid + 1);   // taps for positions 4t+2, 4t+3

    // ---- stage as half4 quads: 2x STS.128
    {
        Half4 q0, q1, q2, q3;
        q0.h[0] = __floats2half2_rn(v0.x, v1.x);  q0.h[1] = __floats2half2_rn(v2.x, v3.x);
        q1.h[0] = __floats2half2_rn(v0.y, v1.y);  q1.h[1] = __floats2half2_rn(v2.y, v3.y);
        q2.h[0] = __floats2half2_rn(v0.z, v1.z);  q2.h[1] = __floats2half2_rn(v2.z, v3.z);
        q3.h[0] = __floats2half2_rn(v0.w, v1.w);  q3.h[1] = __floats2half2_rn(v2.w, v3.w);
        uint4* sd = (uint4*)&s[4 * tid];
        sd[0] = make_uint4(q0.u.x, q0.u.y, q1.u.x, q1.u.y);
        sd[1] = make_uint4(q2.u.x, q2.u.y, q3.u.x, q3.u.y);
    }

    // ---- unpack taps (register-only; overlaps barrier wait)
    const float inv = 1.f / 65535.f;
    int   c0[4];
    float fx[4], fy[4];
    c0[0] = (int)(T01.x & 0xFFFFu);  fx[0] = (float)(T01.x >> 16) * inv;  fy[0] = (float)(T01.y & 0xFFFFu) * inv;
    c0[1] = (int)(T01.z & 0xFFFFu);  fx[1] = (float)(T01.z >> 16) * inv;  fy[1] = (float)(T01.w & 0xFFFFu) * inv;
    c0[2] = (int)(T23.x & 0xFFFFu);  fx[2] = (float)(T23.x >> 16) * inv;  fy[2] = (float)(T23.y & 0xFFFFu) * inv;
    c0[3] = (int)(T23.z & 0xFFFFu);  fx[3] = (float)(T23.z >> 16) * inv;  fy[3] = (float)(T23.w & 0xFFFFu) * inv;
    __syncthreads();

    // ---- gather + math: per position 4 corners (LDS.64), fp32 accumulate
    float4 oc0, oc1, oc2, oc3;
    float* po0 = (float*)&oc0;
    float* po1 = (float*)&oc1;
    float* po2 = (float*)&oc2;
    float* po3 = (float*)&oc3;
#pragma unroll
    for (int p = 0; p < 4; ++p) {
        int c = c0[p];
        Half4 t0, t1, t2, t3;
        t0.u = s[c];
        t1.u = s[c + 1];
        t2.u = s[c + 64];
        t3.u = s[c + 65];

        float w0 = (1.f - fx[p]) * fx[p];
        float w1 = (1.f - fx[p]) * fy[p];
        float w2 = fx[p] * fx[p];
        float w3 = fx[p] * fy[p];

        float2 a01 = __half22float2(t0.h[0]), a23 = __half22float2(t0.h[1]);
        float2 b01 = __half22float2(t1.h[0]), b23 = __half22float2(t1.h[1]);
        float2 c01 = __half22float2(t2.h[0]), c23 = __half22float2(t2.h[1]);
        float2 d01 = __half22float2(t3.h[0]), d23 = __half22float2(t3.h[1]);

        po0[p] = w0 * a01.x + w1 * b01.x + w2 * c01.x + w3 * d01.x;
        po1[p] = w0 * a01.y + w1 * b01.y + w2 * c01.y + w3 * d01.y;
        po2[p] = w0 * a23.x + w1 * b23.x + w2 * c23.x + w3 * d23.x;
        po3[p] = w0 * a23.y + w1 * b23.y + w2 * c23.y + w3 * d23.y;
    }

    float4* ob = (float4*)(out + (size_t)(n * C_ + ch0) * HW_);
    const int q = HW_ / 4;
    ob[0 * q + tid] = oc0;
    ob[1 * q + tid] = oc1;
    ob[2 * q + tid] = oc2;
    ob[3 * q + tid] = oc3;
}

extern "C" void kernel_launch(void* const* d_in, const int* in_sizes, int n_in,
                              void* d_out, int out_size) {
    const float* x    = (const float*)d_in[0];   // (4, 128, 4096) f32
    const float* grid = (const float*)d_in[1];   // (4, 64, 64, 2) f32
    float* out = (float*)d_out;                  // (4, 128, 4096) f32

    prep_kernel<<<8, 256>>>(grid);
    gather_kernel<<<N_ * (C_ / 4), 1024>>>(x, out);
}